// round 9
// baseline (speedup 1.0000x reference)
#include <cuda_runtime.h>
#include <cuda_bf16.h>
#include <math.h>
#include <stdint.h>

constexpr int kD = 2048, kE = 32, kK = 8, kI = 1024, kMaxT = 8192;
constexpr int kMaxRows = kMaxT * kK;   // 65536

// ---------------- scratch (R6-proven set; DO NOT grow) ----------------
__device__ int   g_topi[kMaxRows];
__device__ float g_topw[kMaxRows];
__device__ int   g_rowtok[kMaxRows];
__device__ float g_rowscale[kMaxRows];
__device__ int   g_counts[kE];
__device__ int   g_offsets[kE + 1];
__device__ int   g_cursor[kE];
__device__ float g_sumprob[kE];
__device__ __align__(16) float g_H[(size_t)kMaxRows * kI];   // 256 MB scratch

// ---------------- helpers ----------------
__device__ __forceinline__ uint32_t smem_u32(const void* p) {
    uint32_t a;
    asm("{ .reg .u64 t; cvta.to.shared.u64 t, %1; cvt.u32.u64 %0, t; }" : "=r"(a) : "l"(p));
    return a;
}
__device__ __forceinline__ void mma_bf16(float* c, const uint32_t* a, const uint32_t* b) {
    asm volatile(
        "mma.sync.aligned.m16n8k16.row.col.f32.bf16.bf16.f32 "
        "{%0,%1,%2,%3}, {%4,%5,%6,%7}, {%8,%9}, {%0,%1,%2,%3};"
        : "+f"(c[0]), "+f"(c[1]), "+f"(c[2]), "+f"(c[3])
        : "r"(a[0]), "r"(a[1]), "r"(a[2]), "r"(a[3]), "r"(b[0]), "r"(b[1]));
}
__device__ __forceinline__ void ldsm4(uint32_t* r, uint32_t addr) {
    asm volatile("ldmatrix.sync.aligned.m8n8.x4.shared.b16 {%0,%1,%2,%3}, [%4];"
                 : "=r"(r[0]), "=r"(r[1]), "=r"(r[2]), "=r"(r[3]) : "r"(addr));
}
__device__ __forceinline__ uint32_t pack_hi2(float a, float b) {
    return (uint32_t)__bfloat16_as_ushort(__float2bfloat16(a)) |
           ((uint32_t)__bfloat16_as_ushort(__float2bfloat16(b)) << 16);
}
__device__ __forceinline__ uint32_t pack_lo2(float a, float b) {
    float ra = a - __bfloat162float(__float2bfloat16(a));
    float rb = b - __bfloat162float(__float2bfloat16(b));
    return (uint32_t)__bfloat16_as_ushort(__float2bfloat16(ra)) |
           ((uint32_t)__bfloat16_as_ushort(__float2bfloat16(rb)) << 16);
}

// ---------------- reset / router / bookkeeping (verbatim) ----------------
__global__ void zero_kernel(float* __restrict__ out, size_t n) {
    size_t i = (size_t)blockIdx.x * blockDim.x + threadIdx.x;
    size_t stride = (size_t)gridDim.x * blockDim.x;
    for (; i < n; i += stride) out[i] = 0.f;
    if (blockIdx.x == 0 && threadIdx.x < kE) {
        g_counts[threadIdx.x] = 0;
        g_cursor[threadIdx.x] = 0;
        g_sumprob[threadIdx.x] = 0.f;
    }
}

__global__ void router_kernel(const float* __restrict__ x,
                              const float* __restrict__ Wgate, int T) {
    int warp = (blockIdx.x * blockDim.x + threadIdx.x) >> 5;
    int lane = threadIdx.x & 31;
    if (warp >= T) return;
    const float* xt = x + (size_t)warp * kD;

    float acc = 0.f;
#pragma unroll 4
    for (int d = 0; d < kD; ++d) acc += xt[d] * Wgate[d * kE + lane];

    float m = acc;
#pragma unroll
    for (int o = 16; o; o >>= 1) m = fmaxf(m, __shfl_xor_sync(0xffffffffu, m, o));
    float p = __expf(acc - m);
    float s = p;
#pragma unroll
    for (int o = 16; o; o >>= 1) s += __shfl_xor_sync(0xffffffffu, s, o);
    atomicAdd(&g_sumprob[lane], p / s);

    float v = acc;
    float topv[kK]; int topi[kK];
#pragma unroll
    for (int k = 0; k < kK; ++k) {
        float bv = v; int bi = lane;
#pragma unroll
        for (int o = 16; o; o >>= 1) {
            float ov = __shfl_xor_sync(0xffffffffu, bv, o);
            int   oi = __shfl_xor_sync(0xffffffffu, bi, o);
            if (ov > bv || (ov == bv && oi < bi)) { bv = ov; bi = oi; }
        }
        topv[k] = bv; topi[k] = bi;
        if (lane == bi) v = -INFINITY;
    }

    float mx = topv[0];
    float w[kK]; float se = 0.f;
#pragma unroll
    for (int k = 0; k < kK; ++k) { w[k] = __expf(topv[k] - mx); se += w[k]; }
#pragma unroll
    for (int k = 0; k < kK; ++k) {
        if (lane == k) {
            g_topi[warp * kK + k] = topi[k];
            g_topw[warp * kK + k] = w[k] / se;
            atomicAdd(&g_counts[topi[k]], 1);
        }
    }
}

__global__ void offsets_kernel() {
    if (threadIdx.x == 0) {
        int s = 0;
        for (int e = 0; e < kE; ++e) { g_offsets[e] = s; s += g_counts[e]; }
        g_offsets[kE] = s;
    }
}

__global__ void scatter_kernel(int T) {
    int idx = blockIdx.x * blockDim.x + threadIdx.x;
    if (idx >= T * kK) return;
    int e = g_topi[idx];
    int pos = g_offsets[e] + atomicAdd(&g_cursor[e], 1);
    g_rowtok[pos]   = idx / kK;
    g_rowscale[pos] = g_topw[idx];
}

__global__ void aux_kernel(float* __restrict__ out, int T, int out_size) {
    if (threadIdx.x == 0 && (size_t)out_size > (size_t)T * kD) {
        float a = 0.f;
        for (int e = 0; e < kE; ++e) a += g_sumprob[e] * (float)g_counts[e];
        out[(size_t)T * kD] = a / ((float)T * (float)T);
    }
}

// =========================================================================
// GEMM1: 128(M) x 128(N), BK=16, 512 threads. Double-buffered dynamic smem:
//   per stage 36864 B: AH@0 AL@6144 GH@12288 GL@18432 UH@24576 UL@30720
//   (pitch 48 B per 16-k row). ldmatrix.x4 fragment loads.
// =========================================================================
constexpr int G1_STG = 36864;
__global__ __launch_bounds__(512, 1) void gemm1_mma(const float* __restrict__ x,
                                                    const float* __restrict__ Wg,
                                                    const float* __restrict__ Wu) {
    extern __shared__ __align__(16) char sm[];
    __shared__ int   toks[128];
    __shared__ float scls[128];
    const int e = blockIdx.z;
    const int base  = g_offsets[e];
    const int count = g_offsets[e + 1] - base;
    const int m0 = blockIdx.y * 128;
    if (m0 >= count) return;
    const int n0 = blockIdx.x * 128;
    const int tid = threadIdx.x, lane = tid & 31, wid = tid >> 5;
    const int wm = wid & 3, wn = wid >> 2, g = lane >> 2, q = lane & 3;
    const uint32_t sb = smem_u32(sm);

    if (tid < 128) {
        int r = m0 + tid;
        toks[tid] = g_rowtok[base + ((r < count) ? r : (count - 1))];
        scls[tid] = (r < count) ? g_rowscale[base + r] : 0.f;
    }
    __syncthreads();

    // ldmatrix per-lane address offsets (within a stage buffer)
    const uint32_t aoff = (uint32_t)((wm * 32 + (lane & 7) + ((lane >> 3) & 1) * 8) * 48
                                     + ((lane >> 4) & 1) * 16);
    const uint32_t boff = (uint32_t)((wn * 32 + (lane & 7) + ((lane >> 4) & 1) * 8) * 48
                                     + ((lane >> 3) & 1) * 16);

    const int arow = tid >> 2, ac4 = tid & 3;       // A fill: 128 rows x 4 float4
    const int bn = tid & 127, bkq = tid >> 7;       // B fill: n fixed, k-quad 0..3
    const float* aLg = x + (size_t)toks[arow] * kD + ac4 * 4;

    float4 ra;
    float rg[4], ru[4];

    auto load = [&](int s) {
        const int k0 = s * 16;
        ra = *(const float4*)(aLg + k0);
        const float* gp = Wg + ((size_t)e * kD + k0 + bkq * 4) * kI + n0 + bn;
        const float* up = Wu + ((size_t)e * kD + k0 + bkq * 4) * kI + n0 + bn;
#pragma unroll
        for (int i = 0; i < 4; ++i) {
            rg[i] = gp[(size_t)i * kI];
            ru[i] = up[(size_t)i * kI];
        }
    };
    auto store = [&](int buf) {
        char* bb = sm + buf * G1_STG;
        {
            uint32_t o = (uint32_t)(arow * 48 + ac4 * 8);
            *(uint32_t*)(bb + o)            = pack_hi2(ra.x, ra.y);
            *(uint32_t*)(bb + o + 4)        = pack_hi2(ra.z, ra.w);
            *(uint32_t*)(bb + 6144 + o)     = pack_lo2(ra.x, ra.y);
            *(uint32_t*)(bb + 6144 + o + 4) = pack_lo2(ra.z, ra.w);
        }
        {
            uint32_t o = (uint32_t)(bn * 48 + bkq * 8);
            *(uint32_t*)(bb + 12288 + o)     = pack_hi2(rg[0], rg[1]);
            *(uint32_t*)(bb + 12288 + o + 4) = pack_hi2(rg[2], rg[3]);
            *(uint32_t*)(bb + 18432 + o)     = pack_lo2(rg[0], rg[1]);
            *(uint32_t*)(bb + 18432 + o + 4) = pack_lo2(rg[2], rg[3]);
            *(uint32_t*)(bb + 24576 + o)     = pack_hi2(ru[0], ru[1]);
            *(uint32_t*)(bb + 24576 + o + 4) = pack_hi2(ru[2], ru[3]);
            *(uint32_t*)(bb + 30720 + o)     = pack_lo2(ru[0], ru[1]);
            *(uint32_t*)(bb + 30720 + o + 4) = pack_lo2(ru[2], ru[3]);
        }
    };

    float cg[2][4][4] = {}, cu[2][4][4] = {};
    load(0); store(0);
    __syncthreads();

    const int S = kD / 16;   // 128
    int buf = 0;
    for (int s = 0; s < S; ++s) {
        if (s + 1 < S) load(s + 1);
        const uint32_t bb = sb + buf * G1_STG;
        uint32_t ah[2][4], al[2][4];
#pragma unroll
        for (int mt = 0; mt < 2; ++mt) {
            ldsm4(ah[mt], bb + aoff + mt * 768);
            ldsm4(al[mt], bb + 6144 + aoff + mt * 768);
        }
#pragma unroll
        for (int jp = 0; jp < 2; ++jp) {
            uint32_t gh[4], gl[4], uh[4], ul[4];
            ldsm4(gh, bb + 12288 + boff + jp * 768);
            ldsm4(gl, bb + 18432 + boff + jp * 768);
            ldsm4(uh, bb + 24576 + boff + jp * 768);
            ldsm4(ul, bb + 30720 + boff + jp * 768);
#pragma unroll
            for (int mt = 0; mt < 2; ++mt) {
                mma_bf16(cg[mt][jp * 2],     ah[mt], &gh[0]);
                mma_bf16(cg[mt][jp * 2],     ah[mt], &gl[0]);
                mma_bf16(cg[mt][jp * 2],     al[mt], &gh[0]);
                mma_bf16(cg[mt][jp * 2 + 1], ah[mt], &gh[2]);
                mma_bf16(cg[mt][jp * 2 + 1], ah[mt], &gl[2]);
                mma_bf16(cg[mt][jp * 2 + 1], al[mt], &gh[2]);
                mma_bf16(cu[mt][jp * 2],     ah[mt], &uh[0]);
                mma_bf16(cu[mt][jp * 2],     ah[mt], &ul[0]);
                mma_bf16(cu[mt][jp * 2],     al[mt], &uh[0]);
                mma_bf16(cu[mt][jp * 2 + 1], ah[mt], &uh[2]);
                mma_bf16(cu[mt][jp * 2 + 1], ah[mt], &ul[2]);
                mma_bf16(cu[mt][jp * 2 + 1], al[mt], &uh[2]);
            }
        }
        if (s + 1 < S) store(buf ^ 1);
        __syncthreads();
        buf ^= 1;
    }

    // epilogue: H = silu(gate) * up * routing weight
#pragma unroll
    for (int mt = 0; mt < 2; ++mt)
#pragma unroll
        for (int h = 0; h < 2; ++h) {
            int rl = wm * 32 + mt * 16 + g + h * 8;
            if (m0 + rl < count) {
                float sc = scls[rl];
                float* dst = g_H + (size_t)(base + m0 + rl) * kI + n0 + wn * 32 + q * 2;
#pragma unroll
                for (int j = 0; j < 4; ++j) {
                    float g0 = cg[mt][j][2 * h], g1 = cg[mt][j][2 * h + 1];
                    float u0 = cu[mt][j][2 * h], u1 = cu[mt][j][2 * h + 1];
                    float h0 = g0 / (1.f + __expf(-g0)) * u0 * sc;
                    float h1 = g1 / (1.f + __expf(-g1)) * u1 * sc;
                    *(float2*)(dst + j * 8) = make_float2(h0, h1);
                }
            }
        }
}

// =========================================================================
// GEMM2: 128(M) x 128(N), BK=16, 256 threads. Double-buffered dynamic smem:
//   per stage 24576 B: AH@0 AL@6144 BH@12288 BL@18432. ldmatrix.x4.
// Warps: wm=wid&3 (32 rows), wn=wid>>2 in 0..1 (64 cols, 4 j-pairs).
// =========================================================================
constexpr int G2_STG = 24576;
__global__ __launch_bounds__(256) void gemm2_mma(float* __restrict__ out,
                                                 const float* __restrict__ Wd) {
    extern __shared__ __align__(16) char sm[];
    __shared__ int toks[128];
    const int e = blockIdx.z;
    const int base  = g_offsets[e];
    const int count = g_offsets[e + 1] - base;
    const int m0 = blockIdx.y * 128;
    if (m0 >= count) return;
    const int n0 = blockIdx.x * 128;
    const int tid = threadIdx.x, lane = tid & 31, wid = tid >> 5;
    const int wm = wid & 3, wn = wid >> 2, g = lane >> 2, q = lane & 3;
    const uint32_t sb = smem_u32(sm);

    if (tid < 128) {
        int r = m0 + tid;
        toks[tid] = g_rowtok[base + ((r < count) ? r : (count - 1))];
    }
    __syncthreads();

    const uint32_t aoff = (uint32_t)((wm * 32 + (lane & 7) + ((lane >> 3) & 1) * 8) * 48
                                     + ((lane >> 4) & 1) * 16);
    const uint32_t boff = (uint32_t)((wn * 64 + (lane & 7) + ((lane >> 4) & 1) * 8) * 48
                                     + ((lane >> 3) & 1) * 16);

    const int arow = tid >> 1, ah8 = (tid & 1) * 8;   // A: 128 rows, 8-k halves
    const int bn = tid & 127, bk8 = (tid >> 7) * 8;   // B: n fixed, 8-k halves
    const int arl = (m0 + arow < count) ? (m0 + arow) : (count - 1);
    const float* aptr = g_H + (size_t)(base + arl) * kI + ah8;

    float4 ra0, ra1;
    float rb[8];

    auto load = [&](int s) {
        const int k0 = s * 16;
        ra0 = *(const float4*)(aptr + k0);
        ra1 = *(const float4*)(aptr + k0 + 4);
        const float* bp = Wd + ((size_t)e * kI + k0 + bk8) * kD + n0 + bn;
#pragma unroll
        for (int i = 0; i < 8; ++i) rb[i] = bp[(size_t)i * kD];
    };
    auto store = [&](int buf) {
        char* bb = sm + buf * G2_STG;
        {
            uint32_t o = (uint32_t)(arow * 48 + ah8 * 2);
            *(uint32_t*)(bb + o)             = pack_hi2(ra0.x, ra0.y);
            *(uint32_t*)(bb + o + 4)         = pack_hi2(ra0.z, ra0.w);
            *(uint32_t*)(bb + o + 8)         = pack_hi2(ra1.x, ra1.y);
            *(uint32_t*)(bb + o + 12)        = pack_hi2(ra1.z, ra1.w);
            *(uint32_t*)(bb + 6144 + o)      = pack_lo2(ra0.x, ra0.y);
            *(uint32_t*)(bb + 6144 + o + 4)  = pack_lo2(ra0.z, ra0.w);
            *(uint32_t*)(bb + 6144 + o + 8)  = pack_lo2(ra1.x, ra1.y);
            *(uint32_t*)(bb + 6144 + o + 12) = pack_lo2(ra1.z, ra1.w);
        }
        {
            uint32_t o = (uint32_t)(bn * 48 + bk8 * 2);
            *(uint32_t*)(bb + 12288 + o)      = pack_hi2(rb[0], rb[1]);
            *(uint32_t*)(bb + 12288 + o + 4)  = pack_hi2(rb[2], rb[3]);
            *(uint32_t*)(bb + 12288 + o + 8)  = pack_hi2(rb[4], rb[5]);
            *(uint32_t*)(bb + 12288 + o + 12) = pack_hi2(rb[6], rb[7]);
            *(uint32_t*)(bb + 18432 + o)      = pack_lo2(rb[0], rb[1]);
            *(uint32_t*)(bb + 18432 + o + 4)  = pack_lo2(rb[2], rb[3]);
            *(uint32_t*)(bb + 18432 + o + 8)  = pack_lo2(rb[4], rb[5]);
            *(uint32_t*)(bb + 18432 + o + 12) = pack_lo2(rb[6], rb[7]);
        }
    };

    float c[2][8][4] = {};
    load(0); store(0);
    __syncthreads();

    const int S = kI / 16;   // 64
    int buf = 0;
    for (int s = 0; s < S; ++s) {
        if (s + 1 < S) load(s + 1);
        const uint32_t bb = sb + buf * G2_STG;
        uint32_t ah[2][4], al[2][4];
#pragma unroll
        for (int mt = 0; mt < 2; ++mt) {
            ldsm4(ah[mt], bb + aoff + mt * 768);
            ldsm4(al[mt], bb + 6144 + aoff + mt * 768);
        }
#pragma unroll
        for (int jp = 0; jp < 4; ++jp) {
            uint32_t bh[4], bl[4];
            ldsm4(bh, bb + 12288 + boff + jp * 768);
            ldsm4(bl, bb + 18432 + boff + jp * 768);
#pragma unroll
            for (int mt = 0; mt < 2; ++mt) {
                mma_bf16(c[mt][jp * 2],     ah[mt], &bh[0]);
                mma_bf16(c[mt][jp * 2],     ah[mt], &bl[0]);
                mma_bf16(c[mt][jp * 2],     al[mt], &bh[0]);
                mma_bf16(c[mt][jp * 2 + 1], ah[mt], &bh[2]);
                mma_bf16(c[mt][jp * 2 + 1], ah[mt], &bl[2]);
                mma_bf16(c[mt][jp * 2 + 1], al[mt], &bh[2]);
            }
        }
        if (s + 1 < S) store(buf ^ 1);
        __syncthreads();
        buf ^= 1;
    }

#pragma unroll
    for (int mt = 0; mt < 2; ++mt)
#pragma unroll
        for (int h = 0; h < 2; ++h) {
            int rl = wm * 32 + mt * 16 + g + h * 8;
            if (m0 + rl < count) {
                int tok = toks[rl];
                float* op = out + (size_t)tok * kD + n0 + wn * 64 + q * 2;
#pragma unroll
                for (int j = 0; j < 8; ++j) {
                    atomicAdd(&op[j * 8],     c[mt][j][2 * h]);
                    atomicAdd(&op[j * 8 + 1], c[mt][j][2 * h + 1]);
                }
            }
        }
}

// ---------------- launch ----------------
extern "C" void kernel_launch(void* const* d_in, const int* in_sizes, int n_in,
                              void* d_out, int out_size) {
    const float* x     = (const float*)d_in[0];
    const float* Wgate = (const float*)d_in[1];
    const float* Wg    = (const float*)d_in[2];
    const float* Wu    = (const float*)d_in[3];
    const float* Wd    = (const float*)d_in[4];
    float* out = (float*)d_out;

    const int T = in_sizes[0] / kD;

    cudaFuncSetAttribute(gemm1_mma, cudaFuncAttributeMaxDynamicSharedMemorySize, 2 * G1_STG);
    cudaFuncSetAttribute(gemm2_mma, cudaFuncAttributeMaxDynamicSharedMemorySize, 2 * G2_STG);

    zero_kernel<<<2048, 256>>>(out, (size_t)out_size);
    router_kernel<<<(T + 7) / 8, 256>>>(x, Wgate, T);
    offsets_kernel<<<1, 32>>>();
    scatter_kernel<<<(T * kK + 255) / 256, 256>>>(T);
    aux_kernel<<<1, 32>>>(out, T, out_size);

    gemm1_mma<<<dim3(kI / 128, kMaxT / 128, kE), 512, 2 * G1_STG>>>(x, Wg, Wu);
    gemm2_mma<<<dim3(kD / 128, kMaxT / 128, kE), 256, 2 * G2_STG>>>(out, Wd);
}